// round 9
// baseline (speedup 1.0000x reference)
#include <cuda_runtime.h>

#define K_CODES 16384
#define NSAMP   4096
#define DIM     14
#define HW      1024
#define Q_ELEMS 57344            // 4 * 14 * 1024
#define WPB     8                // warps (= samples) per block, kernel A

// Module-load zero-initialized; every call restores zeros behind itself so
// each execution (eager correctness run or graph replay) starts identically.
__device__ __align__(16) float g_avg[K_CODES];
__device__ float g_ent_sum;

__device__ __forceinline__ float warp_sum(float v) {
#pragma unroll
    for (int off = 16; off > 0; off >>= 1)
        v += __shfl_xor_sync(0xffffffffu, v, off);
    return v;
}

// ---------------------------------------------------------------------------
// Kernel A (unchanged from the measured-best R8 version):
// ONE WARP PER SAMPLE. lane j<14 owns dim j. Ballot -> big-endian index;
// shuffle reductions -> norm and the EXACT closed-form entropy (the softmax
// over +-1 codes factorizes into per-dim Bernoullis):
//   a_j = 400|xn_j|,  logS = sum log(1+e^-a_j),  H = logS + sum a_j*e_j/(1+e_j)
// Survivor scatter into g_avg: lane = subset mask of dims with a_j < 30
// (dropped probs < e^-30, below fp32 noise in the reference itself).
// ---------------------------------------------------------------------------
__global__ __launch_bounds__(32 * WPB) void lfq_main(const float* __restrict__ x,
                                                     float* __restrict__ out) {
    __shared__ float sc[WPB][DIM];
    __shared__ int   st[WPB][DIM];
    __shared__ float wents[WPB];

    const int wid  = threadIdx.x >> 5;
    const int lane = threadIdx.x & 31;
    const int s    = blockIdx.x * WPB + wid;    // sample id
    const int b    = s >> 10;
    const int n    = s & (HW - 1);

    float v = 0.0f;
    if (lane < DIM) {
        v = x[(b * DIM + lane) * HW + n];
        out[(b * DIM + lane) * HW + n] = (v > 0.0f) ? 1.0f : -1.0f;
    }

    const float inv = rsqrtf(warp_sum(v * v));

    const unsigned bal = __ballot_sync(0xffffffffu, v > 0.0f) & 0x3FFFu;
    const int idx = (int)(__brev(bal) >> 18);    // big-endian bit order
    if (lane == 0) out[Q_ELEMS + 1 + s] = (float)idx;

    // closed-form softmax stats (fast-math: 2^-21 rel err vs 1e-3 budget)
    const float a = (lane < DIM) ? 400.0f * fabsf(v) * inv : 1e30f;
    const float e = __expf(-a);                  // exactly 0 for pad lanes
    const float logS = warp_sum(__logf(1.0f + e));
    const float ent  = logS + warp_sum(__fdividef(a * e, 1.0f + e));
    if (lane == 0) wents[wid] = ent;

    // rank the "small" (flippable) dims into shared
    const bool small = (lane < DIM) && (a < 30.0f);
    const unsigned bm = __ballot_sync(0xffffffffu, small);
    const int m = __popc(bm);
    if (small) {
        const int rank = __popc(bm & ((1u << lane) - 1u));
        sc[wid][rank] = a;
        st[wid][rank] = 1 << (13 - lane);
    }
    __syncwarp();

    // survivor scatter: lane = subset mask (one pass for ~95% of samples)
    const float invS = __expf(-logS);
    const int nm = 1 << m;
    for (int mask = lane; mask < nm; mask += 32) {
        float c = 0.0f;
        int tog = 0;
        for (int j = 0; j < m; j++)
            if ((mask >> j) & 1) { c += sc[wid][j]; tog ^= st[wid][j]; }
        if (c < 30.0f)
            atomicAdd(&g_avg[idx ^ tog], __expf(-c) * invS);
    }

    // block-level entropy reduction -> one atomic per block
    __syncthreads();
    if (threadIdx.x < WPB) {
        float t = wents[threadIdx.x];
#pragma unroll
        for (int off = WPB / 2; off > 0; off >>= 1)
            t += __shfl_xor_sync((1u << WPB) - 1u, t, off);
        if (threadIdx.x == 0) atomicAdd(&g_ent_sum, t);
    }
}

// ---------------------------------------------------------------------------
// Kernel B: ONE block, 1024 threads. 4 float4 chunks per thread (MLP=4),
// MUFU __logf, two-level block reduce; thread 0 writes el directly and
// resets g_ent_sum. Kernel-boundary ordering makes all of A's atomics
// visible — no fences, no tickets, no cross-block finalize chain.
// ---------------------------------------------------------------------------
__global__ __launch_bounds__(1024) void lfq_hist(float* __restrict__ out) {
    __shared__ float wsum[32];
    const int tid = threadIdx.x;
    const float sN = 1.0f / (float)NSAMP;
    const float4 z4 = make_float4(0.f, 0.f, 0.f, 0.f);

    float ms = 0.0f;
#pragma unroll
    for (int i = 0; i < K_CODES / 4 / 1024; i++) {       // 4 iterations
        const int i4 = i * 1024 + tid;                   // coalesced
        float4 a4 = reinterpret_cast<float4*>(g_avg)[i4];
        reinterpret_cast<float4*>(g_avg)[i4] = z4;       // restore zeros
        ms += (a4.x * sN) * __logf(a4.x * sN + 1e-9f)
            + (a4.y * sN) * __logf(a4.y * sN + 1e-9f)
            + (a4.z * sN) * __logf(a4.z * sN + 1e-9f)
            + (a4.w * sN) * __logf(a4.w * sN + 1e-9f);
    }

    ms = warp_sum(ms);
    if ((tid & 31) == 0) wsum[tid >> 5] = ms;
    __syncthreads();
    if (tid < 32) {
        float t = wsum[tid];
#pragma unroll
        for (int off = 16; off > 0; off >>= 1)
            t += __shfl_xor_sync(0xffffffffu, t, off);
        if (tid == 0) {
            const float es = g_ent_sum;                  // ordered by kernel boundary
            // el = entro_mean - mean_entro = es/N + sum a*log(a+eps)
            out[Q_ELEMS] = es * (1.0f / (float)NSAMP) + t;
            g_ent_sum = 0.0f;                            // reset for next replay
        }
    }
}

extern "C" void kernel_launch(void* const* d_in, const int* in_sizes, int n_in,
                              void* d_out, int out_size) {
    const float* x = (const float*)d_in[0];
    float* out = (float*)d_out;

    lfq_main<<<NSAMP / WPB, 32 * WPB>>>(x, out);
    lfq_hist<<<1, 1024>>>(out);
}

// round 10
// speedup vs baseline: 1.2379x; 1.2379x over previous
#include <cuda_runtime.h>

#define K_CODES 16384
#define NSAMP   4096
#define DIM     14
#define HW      1024
#define Q_ELEMS 57344            // 4 * 14 * 1024
#define WPB     8                // warps (= samples) per block, kernel A
#define TBLK    16               // blocks, kernel B (16*256 = 4096 threads)

// Module-load zero-initialized; every call restores zeros behind itself so
// each execution (eager correctness run or graph replay) starts identically.
__device__ __align__(16) float g_avg[K_CODES];
__device__ float g_ent_sum;
__device__ float g_hist_sum;
__device__ int   g_done;

__device__ __forceinline__ float warp_sum(float v) {
#pragma unroll
    for (int off = 16; off > 0; off >>= 1)
        v += __shfl_xor_sync(0xffffffffu, v, off);
    return v;
}

// ---------------------------------------------------------------------------
// Kernel A (primary): entropy + survivor scatter ONLY (no output writes).
// ONE WARP PER SAMPLE. lane j<14 owns dim j; shuffle reductions give the
// EXACT closed-form entropy (softmax over +-1 codes factorizes into per-dim
// Bernoullis): a_j = 400|xn_j|, logS = sum log(1+e^-a_j),
// H = logS + sum a_j e_j/(1+e_j). Survivor scatter into g_avg: lane = subset
// mask of dims with a_j < 30 (dropped probs < e^-30, below fp32 noise).
// ---------------------------------------------------------------------------
__global__ __launch_bounds__(32 * WPB) void lfq_scatter(const float* __restrict__ x) {
    __shared__ float sc[WPB][DIM];
    __shared__ int   st[WPB][DIM];
    __shared__ float wents[WPB];

    const int wid  = threadIdx.x >> 5;
    const int lane = threadIdx.x & 31;
    const int s    = blockIdx.x * WPB + wid;    // sample id
    const int b    = s >> 10;
    const int n    = s & (HW - 1);

    float v = 0.0f;
    if (lane < DIM) v = x[(b * DIM + lane) * HW + n];

    const float inv = rsqrtf(warp_sum(v * v));

    const unsigned bal = __ballot_sync(0xffffffffu, v > 0.0f) & 0x3FFFu;
    const int idx = (int)(__brev(bal) >> 18);    // big-endian bit order

    const float a = (lane < DIM) ? 400.0f * fabsf(v) * inv : 1e30f;
    const float e = __expf(-a);                  // exactly 0 for pad lanes
    const float logS = warp_sum(__logf(1.0f + e));
    const float ent  = logS + warp_sum(__fdividef(a * e, 1.0f + e));
    if (lane == 0) wents[wid] = ent;

    const bool small = (lane < DIM) && (a < 30.0f);
    const unsigned bm = __ballot_sync(0xffffffffu, small);
    const int m = __popc(bm);
    if (small) {
        const int rank = __popc(bm & ((1u << lane) - 1u));
        sc[wid][rank] = a;
        st[wid][rank] = 1 << (13 - lane);
    }
    __syncwarp();

    const float invS = __expf(-logS);
    const int nm = 1 << m;
    for (int mask = lane; mask < nm; mask += 32) {
        float c = 0.0f;
        int tog = 0;
        for (int j = 0; j < m; j++)
            if ((mask >> j) & 1) { c += sc[wid][j]; tog ^= st[wid][j]; }
        if (c < 30.0f)
            atomicAdd(&g_avg[idx ^ tog], __expf(-c) * invS);
    }

    __syncthreads();
    if (threadIdx.x < WPB) {
        float t = wents[threadIdx.x];
#pragma unroll
        for (int off = WPB / 2; off > 0; off >>= 1)
            t += __shfl_xor_sync((1u << WPB) - 1u, t, off);
        if (threadIdx.x == 0) atomicAdd(&g_ent_sum, t);
    }
}

// ---------------------------------------------------------------------------
// Kernel B (secondary, PDL): overlaps with A.
// PRE-WAIT (independent of A): one sample per thread — q = sign(x) writes
//   (coalesced across lanes: consecutive threads = consecutive n) + index.
// griddepcontrol.wait  (A complete + memflush -> g_avg/g_ent_sum visible)
// POST-WAIT: one float4 histogram chunk per thread, MUFU __logf, zero behind
//   itself; last-ticket block combines scalars into el and resets state.
// ---------------------------------------------------------------------------
__global__ __launch_bounds__(256) void lfq_tail(const float* __restrict__ x,
                                                float* __restrict__ out) {
    __shared__ float wsum[8];
    const int tid  = threadIdx.x;
    const int gtid = blockIdx.x * 256 + tid;     // 0..4095
    const int b    = gtid >> 10;
    const int n    = gtid & (HW - 1);

    // ---- pre-wait: q + index for sample gtid ----
    const float* xs = x   + b * DIM * HW + n;
    float*       qo = out + b * DIM * HW + n;
    int idx = 0;
#pragma unroll
    for (int j = 0; j < DIM; j++) {
        const float v = xs[j * HW];
        const bool pos = v > 0.0f;
        qo[j * HW] = pos ? 1.0f : -1.0f;
        if (pos) idx |= (1 << (13 - j));
    }
    out[Q_ELEMS + 1 + gtid] = (float)idx;

    // ---- wait for primary grid (full completion + memory flush) ----
    asm volatile("griddepcontrol.wait;" ::: "memory");

    // ---- post-wait: histogram fold (one float4 per thread) ----
    const float sN = 1.0f / (float)NSAMP;
    float4 a4 = reinterpret_cast<float4*>(g_avg)[gtid];
    reinterpret_cast<float4*>(g_avg)[gtid] = make_float4(0.f, 0.f, 0.f, 0.f);
    float ms = (a4.x * sN) * __logf(a4.x * sN + 1e-9f)
             + (a4.y * sN) * __logf(a4.y * sN + 1e-9f)
             + (a4.z * sN) * __logf(a4.z * sN + 1e-9f)
             + (a4.w * sN) * __logf(a4.w * sN + 1e-9f);

    ms = warp_sum(ms);
    if ((tid & 31) == 0) wsum[tid >> 5] = ms;
    __syncthreads();
    if (tid < 8) {
        float t = wsum[tid];
#pragma unroll
        for (int off = 4; off > 0; off >>= 1)
            t += __shfl_xor_sync(0xffu, t, off);
        if (tid == 0) {
            atomicAdd(&g_hist_sum, t);
            __threadfence();
            const int d = atomicAdd(&g_done, 1);
            if (d == TBLK - 1) {
                const float hs = atomicAdd(&g_hist_sum, 0.0f);
                const float es = atomicAdd(&g_ent_sum, 0.0f);
                // el = entro_mean - mean_entro = es/N + sum a*log(a+eps)
                out[Q_ELEMS] = es * (1.0f / (float)NSAMP) + hs;
                g_hist_sum = 0.0f;
                g_ent_sum  = 0.0f;
                g_done     = 0;
            }
        }
    }
}

extern "C" void kernel_launch(void* const* d_in, const int* in_sizes, int n_in,
                              void* d_out, int out_size) {
    const float* x = (const float*)d_in[0];
    float* out = (float*)d_out;

    lfq_scatter<<<NSAMP / WPB, 32 * WPB>>>(x);

    // Secondary with Programmatic Stream Serialization: may start while the
    // primary runs; griddepcontrol.wait inside provides the dependency.
    cudaLaunchConfig_t cfg = {};
    cfg.gridDim  = dim3(TBLK);
    cfg.blockDim = dim3(256);
    cfg.stream   = 0;
    cudaLaunchAttribute attr[1];
    attr[0].id = cudaLaunchAttributeProgrammaticStreamSerialization;
    attr[0].val.programmaticStreamSerializationAllowed = 1;
    cfg.attrs    = attr;
    cfg.numAttrs = 1;
    cudaLaunchKernelEx(&cfg, lfq_tail, x, out);
}

// round 12
// speedup vs baseline: 1.4293x; 1.1547x over previous
#include <cuda_runtime.h>

#define K_CODES 16384
#define NSAMP   4096
#define DIM     14
#define HW      1024
#define Q_ELEMS 57344            // 4 * 14 * 1024
#define WPB     8                // warps (= samples) per block, kernel A
#define TBLK    16               // blocks, kernel B (16*256 = 4096 threads)

// Module-load zero-initialized; every call restores zeros behind itself so
// each execution (eager correctness run or graph replay) starts identically.
__device__ __align__(16) float g_avg[K_CODES];
__device__ float g_ent_sum;
__device__ float g_hist_sum;
__device__ int   g_done;

__device__ __forceinline__ float warp_sum(float v) {
#pragma unroll
    for (int off = 16; off > 0; off >>= 1)
        v += __shfl_xor_sync(0xffffffffu, v, off);
    return v;
}

// ---------------------------------------------------------------------------
// Kernel A (primary): entropy + survivor scatter ONLY.
// Fires the PDL trigger AT ENTRY so the dependent kernel can start its
// A-independent work (q/index writes) concurrently.
// ONE WARP PER SAMPLE. lane j<14 owns dim j; shuffle reductions give the
// EXACT closed-form entropy (softmax over +-1 codes factorizes into per-dim
// Bernoullis): a_j = 400|xn_j|, logS = sum log(1+e^-a_j),
// H = logS + sum a_j e_j/(1+e_j). Survivor scatter into g_avg: lane = subset
// mask of dims with a_j < 30 (dropped probs < e^-30, below fp32 noise).
// ---------------------------------------------------------------------------
__global__ __launch_bounds__(32 * WPB) void lfq_scatter(const float* __restrict__ x) {
    // PDL trigger: allow the dependent grid to launch now. Its wait still
    // blocks until this grid fully completes + flushes, so g_avg/g_ent_sum
    // consumption stays correctly ordered.
    asm volatile("griddepcontrol.launch_dependents;" ::: "memory");

    __shared__ float sc[WPB][DIM];
    __shared__ int   st[WPB][DIM];
    __shared__ float wents[WPB];

    const int wid  = threadIdx.x >> 5;
    const int lane = threadIdx.x & 31;
    const int s    = blockIdx.x * WPB + wid;    // sample id
    const int b    = s >> 10;
    const int n    = s & (HW - 1);

    float v = 0.0f;
    if (lane < DIM) v = x[(b * DIM + lane) * HW + n];

    const float inv = rsqrtf(warp_sum(v * v));

    const unsigned bal = __ballot_sync(0xffffffffu, v > 0.0f) & 0x3FFFu;
    const int idx = (int)(__brev(bal) >> 18);    // big-endian bit order

    const float a = (lane < DIM) ? 400.0f * fabsf(v) * inv : 1e30f;
    const float e = __expf(-a);                  // exactly 0 for pad lanes
    const float logS = warp_sum(__logf(1.0f + e));
    const float ent  = logS + warp_sum(__fdividef(a * e, 1.0f + e));
    if (lane == 0) wents[wid] = ent;

    const bool small = (lane < DIM) && (a < 30.0f);
    const unsigned bm = __ballot_sync(0xffffffffu, small);
    const int m = __popc(bm);
    if (small) {
        const int rank = __popc(bm & ((1u << lane) - 1u));
        sc[wid][rank] = a;
        st[wid][rank] = 1 << (13 - lane);
    }
    __syncwarp();

    const float invS = __expf(-logS);
    const int nm = 1 << m;
    for (int mask = lane; mask < nm; mask += 32) {
        float c = 0.0f;
        int tog = 0;
        for (int j = 0; j < m; j++)
            if ((mask >> j) & 1) { c += sc[wid][j]; tog ^= st[wid][j]; }
        if (c < 30.0f)
            atomicAdd(&g_avg[idx ^ tog], __expf(-c) * invS);
    }

    __syncthreads();
    if (threadIdx.x < WPB) {
        float t = wents[threadIdx.x];
#pragma unroll
        for (int off = WPB / 2; off > 0; off >>= 1)
            t += __shfl_xor_sync((1u << WPB) - 1u, t, off);
        if (threadIdx.x == 0) atomicAdd(&g_ent_sum, t);
    }
}

// ---------------------------------------------------------------------------
// Kernel B (secondary, PDL): starts while A runs (trigger fired at A entry).
// PRE-WAIT (independent of A): one sample per thread — q = sign(x) writes
//   (coalesced: consecutive threads = consecutive n) + index emit.
// griddepcontrol.wait  (A complete + memflush -> g_avg/g_ent_sum visible)
// POST-WAIT: one float4 histogram chunk per thread, MUFU __logf, zero behind
//   itself; last-ticket block combines scalars into el and resets state.
// ---------------------------------------------------------------------------
__global__ __launch_bounds__(256) void lfq_tail(const float* __restrict__ x,
                                                float* __restrict__ out) {
    __shared__ float wsum[8];
    const int tid  = threadIdx.x;
    const int gtid = blockIdx.x * 256 + tid;     // 0..4095
    const int b    = gtid >> 10;
    const int n    = gtid & (HW - 1);

    // ---- pre-wait: q + index for sample gtid (overlaps with A) ----
    const float* xs = x   + b * DIM * HW + n;
    float*       qo = out + b * DIM * HW + n;
    int idx = 0;
#pragma unroll
    for (int j = 0; j < DIM; j++) {
        const float v = xs[j * HW];
        const bool pos = v > 0.0f;
        qo[j * HW] = pos ? 1.0f : -1.0f;
        if (pos) idx |= (1 << (13 - j));
    }
    out[Q_ELEMS + 1 + gtid] = (float)idx;

    // ---- wait for primary grid (full completion + memory flush) ----
    asm volatile("griddepcontrol.wait;" ::: "memory");

    // ---- post-wait: histogram fold (one float4 per thread) ----
    const float sN = 1.0f / (float)NSAMP;
    float4 a4 = reinterpret_cast<float4*>(g_avg)[gtid];
    reinterpret_cast<float4*>(g_avg)[gtid] = make_float4(0.f, 0.f, 0.f, 0.f);
    float ms = (a4.x * sN) * __logf(a4.x * sN + 1e-9f)
             + (a4.y * sN) * __logf(a4.y * sN + 1e-9f)
             + (a4.z * sN) * __logf(a4.z * sN + 1e-9f)
             + (a4.w * sN) * __logf(a4.w * sN + 1e-9f);

    ms = warp_sum(ms);
    if ((tid & 31) == 0) wsum[tid >> 5] = ms;
    __syncthreads();
    if (tid < 8) {
        float t = wsum[tid];
#pragma unroll
        for (int off = 4; off > 0; off >>= 1)
            t += __shfl_xor_sync(0xffu, t, off);
        if (tid == 0) {
            atomicAdd(&g_hist_sum, t);
            __threadfence();
            const int d = atomicAdd(&g_done, 1);
            if (d == TBLK - 1) {
                const float hs = atomicAdd(&g_hist_sum, 0.0f);
                const float es = atomicAdd(&g_ent_sum, 0.0f);
                // el = entro_mean - mean_entro = es/N + sum a*log(a+eps)
                out[Q_ELEMS] = es * (1.0f / (float)NSAMP) + hs;
                g_hist_sum = 0.0f;
                g_ent_sum  = 0.0f;
                g_done     = 0;
            }
        }
    }
}

extern "C" void kernel_launch(void* const* d_in, const int* in_sizes, int n_in,
                              void* d_out, int out_size) {
    const float* x = (const float*)d_in[0];
    float* out = (float*)d_out;

    lfq_scatter<<<NSAMP / WPB, 32 * WPB>>>(x);

    // Secondary with Programmatic Stream Serialization: launches once A's
    // blocks fire griddepcontrol.launch_dependents (at A entry), overlapping
    // B's pre-wait phase with A's execution.
    cudaLaunchConfig_t cfg = {};
    cfg.gridDim  = dim3(TBLK);
    cfg.blockDim = dim3(256);
    cfg.stream   = 0;
    cudaLaunchAttribute attr[1];
    attr[0].id = cudaLaunchAttributeProgrammaticStreamSerialization;
    attr[0].val.programmaticStreamSerializationAllowed = 1;
    cfg.attrs    = attr;
    cfg.numAttrs = 1;
    cudaLaunchKernelEx(&cfg, lfq_tail, x, out);
}